// round 8
// baseline (speedup 1.0000x reference)
#include <cuda_runtime.h>
#include <stdint.h>

// Problem constants
#define NB    32
#define CIN   256
#define HH    56
#define WW    56
#define COUT  256
#define NWORD 8          // 256 channels / 32 bits
#define WPAD  (WW + 2)   // zero-padded columns
#define BN_EPS 1e-5f

// Scratch (no allocations allowed): packed sign bits
__device__ uint32_t g_xp[(size_t)NB * HH * WW * NWORD];   // [n][h][w][word]
__device__ uint32_t g_wp[9 * NWORD * COUT];               // [tap][word][co]

// ---------------------------------------------------------------------------
__global__ void pack_x_kernel(const float* __restrict__ x) {
    int b = blockIdx.x;            // n*56 + h
    int n = b / HH, h = b % HH;
    int t = threadIdx.x;
    if (t >= WW * NWORD) return;
    int wd = t / WW;
    int w  = t % WW;
    const float* xb = x + ((size_t)n * CIN + (size_t)wd * 32) * (HH * WW)
                        + (size_t)h * WW + w;
    uint32_t bits = 0;
    #pragma unroll
    for (int c = 0; c < 32; ++c) {
        float v = __ldg(xb + (size_t)c * (HH * WW));
        bits |= (v > 0.0f) ? (1u << c) : 0u;
    }
    g_xp[((size_t)b * WW + w) * NWORD + wd] = bits;
}

// ---------------------------------------------------------------------------
__global__ void pack_w_kernel(const float* __restrict__ wt) {
    int gid = blockIdx.x * blockDim.x + threadIdx.x;
    if (gid >= 9 * NWORD * COUT) return;
    int co  = gid & (COUT - 1);
    int tw  = gid >> 8;            // tap*8 + wd
    int tap = tw >> 3;
    int wd  = tw & 7;
    const float* wb = wt + ((size_t)co * CIN + (size_t)wd * 32) * 9 + tap;
    uint32_t bits = 0;
    #pragma unroll
    for (int c = 0; c < 32; ++c) {
        float v = __ldg(wb + c * 9);
        bits |= (v > 0.0f) ? (1u << c) : 0u;
    }
    g_wp[gid] = bits;
}

// ---------------------------------------------------------------------------
// CSA: (s, c) = (XOR3, MAJ3) -> 2 LOP3 in SASS
__device__ __forceinline__ void csa(uint32_t& s, uint32_t& c,
                                    uint32_t a, uint32_t b, uint32_t d) {
    s = a ^ b ^ d;
    c = (a & b) | (d & (a ^ b));
}

// ---------------------------------------------------------------------------
// Binary conv + BN. Block per (n,h) row; thread = co.
// Harley-Seal: per word lane, CSA-compress 9 taps -> popc on 4 words instead
// of 9 (weights 1/2/2/4). 72 POPC -> 32 POPC per output.
// ---------------------------------------------------------------------------
__global__ void __launch_bounds__(256, 2)
conv_kernel(const float* __restrict__ gamma, const float* __restrict__ beta,
            const float* __restrict__ rmean, const float* __restrict__ rvar,
            float* __restrict__ out) {
    int b = blockIdx.x;            // n*56 + h
    int n = b / HH, h = b % HH;
    int t = threadIdx.x;           // co

    // Per-thread weight bits
    uint32_t wreg[9][NWORD];
    #pragma unroll
    for (int tap = 0; tap < 9; ++tap)
        #pragma unroll
        for (int wd = 0; wd < NWORD; ++wd)
            wreg[tap][wd] = g_wp[(tap * NWORD + wd) * COUT + t];

    // m[tap] = contribution of a zero-padded tap to the XNOR match count
    int m[9];
    #pragma unroll
    for (int tap = 0; tap < 9; ++tap) {
        int pw = 0;
        #pragma unroll
        for (int wd = 0; wd < NWORD; ++wd) pw += __popc(wreg[tap][wd]);
        m[tap] = 256 - pw;
    }

    // Stage 3 padded input rows: [kh][col 0..57][word 0..7]
    __shared__ uint32_t xs[3][WPAD * NWORD];
    bool r0 = (h > 0), r2 = (h < HH - 1);
    bool rowok[3] = { r0, true, r2 };
    #pragma unroll
    for (int kh = 0; kh < 3; ++kh) {
        if (rowok[kh]) {
            if (t < 2 * NWORD) {
                int c = (t < NWORD) ? 0 : (WPAD - 1);
                xs[kh][c * NWORD + (t & (NWORD - 1))] = 0u;
            }
            const uint32_t* src = &g_xp[((size_t)(n * HH + (h + kh - 1)) * WW) * NWORD];
            for (int i = t; i < WW * NWORD; i += 256)
                xs[kh][NWORD + i] = src[i];
        } else {
            for (int i = t; i < WPAD * NWORD; i += 256)
                xs[kh][i] = 0u;
        }
    }
    __syncthreads();

    // Folded epilogue: out = accx*(-2*iv) + c, accx = total popc(x^w), 72 words
    float iv = gamma[t] * rsqrtf(rvar[t] + BN_EPS);
    float bs = fmaf(-rmean[t], iv, beta[t]);
    int rowcnt    = (int)r0 + 1 + (int)r2;
    int Minv_base = (r0 ? 0 : (m[0] + m[1] + m[2])) + (r2 ? 0 : (m[6] + m[7] + m[8]));
    int Mleft     = (r0 ? m[0] : 0) + m[3] + (r2 ? m[6] : 0);
    int Mright    = (r0 ? m[2] : 0) + m[5] + (r2 ? m[8] : 0);
    int nv_base   = 3 * rowcnt;
    float niv2    = -2.0f * iv;
    float c_mid   = fmaf((float)(4608 - 2 * Minv_base - 256 * nv_base), iv, bs);
    float c_left  = fmaf((float)(4608 - 2 * (Minv_base + Mleft)  - 256 * (nv_base - rowcnt)), iv, bs);
    float c_right = fmaf((float)(4608 - 2 * (Minv_base + Mright) - 256 * (nv_base - rowcnt)), iv, bs);

    float* op = out + (((size_t)n * COUT + t) * HH + h) * WW;

    #pragma unroll 2
    for (int w = 0; w < WW; ++w) {
        int acc1 = 0, acc2 = 0, acc4 = 0;
        #pragma unroll
        for (int half = 0; half < 2; ++half) {
            // load + XOR: 9 taps x 4 words
            uint32_t xv[9][4];
            #pragma unroll
            for (int tap = 0; tap < 9; ++tap) {
                int kh = tap / 3, kw = tap % 3;
                uint4 a = *(const uint4*)&xs[kh][(w + kw) * NWORD + half * 4];
                xv[tap][0] = a.x ^ wreg[tap][half * 4 + 0];
                xv[tap][1] = a.y ^ wreg[tap][half * 4 + 1];
                xv[tap][2] = a.z ^ wreg[tap][half * 4 + 2];
                xv[tap][3] = a.w ^ wreg[tap][half * 4 + 3];
            }
            // per word lane: two-level CSA over the 9 taps
            #pragma unroll
            for (int j = 0; j < 4; ++j) {
                uint32_t s0, c0, s1, c1, s2, c2, ss, sc, cs, cc;
                csa(s0, c0, xv[0][j], xv[1][j], xv[2][j]);
                csa(s1, c1, xv[3][j], xv[4][j], xv[5][j]);
                csa(s2, c2, xv[6][j], xv[7][j], xv[8][j]);
                csa(ss, sc, s0, s1, s2);
                csa(cs, cc, c0, c1, c2);
                acc1 += __popc(ss);
                acc2 += __popc(sc) + __popc(cs);
                acc4 += __popc(cc);
            }
        }
        int accx = acc1 + 2 * acc2 + 4 * acc4;
        float cb = c_mid;
        if (w == 0)      cb = c_left;
        if (w == WW - 1) cb = c_right;
        op[w] = fmaf((float)accx, niv2, cb);
    }
}

// ---------------------------------------------------------------------------
extern "C" void kernel_launch(void* const* d_in, const int* in_sizes, int n_in,
                              void* d_out, int out_size) {
    const float* x     = (const float*)d_in[0];
    const float* wt    = (const float*)d_in[1];
    const float* gamma = (const float*)d_in[2];
    const float* beta  = (const float*)d_in[3];
    const float* rmean = (const float*)d_in[4];
    const float* rvar  = (const float*)d_in[5];
    float* out = (float*)d_out;

    pack_x_kernel<<<NB * HH, 512>>>(x);
    pack_w_kernel<<<(9 * NWORD * COUT + 255) / 256, 256>>>(wt);
    conv_kernel<<<NB * HH, 256>>>(gamma, beta, rmean, rvar, out);
}

// round 9
// speedup vs baseline: 1.0744x; 1.0744x over previous
#include <cuda_runtime.h>
#include <stdint.h>

// Problem constants
#define NB    32
#define CIN   256
#define HH    56
#define WW    56
#define COUT  256
#define NWORD 8          // 256 channels / 32 bits
#define WPAD  (WW + 2)   // zero-padded columns
#define OSROW 57         // padded output row (stride 57 -> conflict-free)
#define BN_EPS 1e-5f

#define SMEM_XS_WORDS (3 * WPAD * NWORD)                  // 1392 u32 = 5568 B
#define SMEM_DYN      (SMEM_XS_WORDS * 4 + COUT * OSROW * 4)  // 63936 B

// Scratch (no allocations allowed): packed sign bits
__device__ uint32_t g_xp[(size_t)NB * HH * WW * NWORD];   // [n][h][w][word]
__device__ uint32_t g_wp[9 * NWORD * COUT];               // [tap][word][co]

// ---------------------------------------------------------------------------
__global__ void pack_x_kernel(const float* __restrict__ x) {
    int b = blockIdx.x;            // n*56 + h
    int n = b / HH, h = b % HH;
    int t = threadIdx.x;
    if (t >= WW * NWORD) return;
    int wd = t / WW;
    int w  = t % WW;
    const float* xb = x + ((size_t)n * CIN + (size_t)wd * 32) * (HH * WW)
                        + (size_t)h * WW + w;
    uint32_t bits = 0;
    #pragma unroll
    for (int c = 0; c < 32; ++c) {
        float v = __ldg(xb + (size_t)c * (HH * WW));
        bits |= (v > 0.0f) ? (1u << c) : 0u;
    }
    g_xp[((size_t)b * WW + w) * NWORD + wd] = bits;
}

// ---------------------------------------------------------------------------
__global__ void pack_w_kernel(const float* __restrict__ wt) {
    int gid = blockIdx.x * blockDim.x + threadIdx.x;
    if (gid >= 9 * NWORD * COUT) return;
    int co  = gid & (COUT - 1);
    int tw  = gid >> 8;            // tap*8 + wd
    int tap = tw >> 3;
    int wd  = tw & 7;
    const float* wb = wt + ((size_t)co * CIN + (size_t)wd * 32) * 9 + tap;
    uint32_t bits = 0;
    #pragma unroll
    for (int c = 0; c < 32; ++c) {
        float v = __ldg(wb + c * 9);
        bits |= (v > 0.0f) ? (1u << c) : 0u;
    }
    g_wp[gid] = bits;
}

// ---------------------------------------------------------------------------
// Binary conv + BN. Block per (n,h) row; thread = co.
// R6 compute loop (direct XOR+POPC, branch-free padded smem, folded BN).
// NEW: outputs staged in smem and written back coalesced.
// ---------------------------------------------------------------------------
__global__ void __launch_bounds__(256, 2)
conv_kernel(const float* __restrict__ gamma, const float* __restrict__ beta,
            const float* __restrict__ rmean, const float* __restrict__ rvar,
            float* __restrict__ out) {
    extern __shared__ uint32_t dynsmem[];
    uint32_t (*xs)[WPAD * NWORD] = (uint32_t (*)[WPAD * NWORD])dynsmem;
    float* os = (float*)(dynsmem + SMEM_XS_WORDS);        // [co][OSROW]

    int b = blockIdx.x;            // n*56 + h
    int n = b / HH, h = b % HH;
    int t = threadIdx.x;           // co

    // Per-thread weight bits
    uint32_t wreg[9][NWORD];
    #pragma unroll
    for (int tap = 0; tap < 9; ++tap)
        #pragma unroll
        for (int wd = 0; wd < NWORD; ++wd)
            wreg[tap][wd] = g_wp[(tap * NWORD + wd) * COUT + t];

    // m[tap] = contribution of a zero-padded tap to the XNOR match count
    int m[9];
    #pragma unroll
    for (int tap = 0; tap < 9; ++tap) {
        int pw = 0;
        #pragma unroll
        for (int wd = 0; wd < NWORD; ++wd) pw += __popc(wreg[tap][wd]);
        m[tap] = 256 - pw;
    }

    // Stage 3 padded input rows: [kh][col 0..57][word 0..7]
    bool r0 = (h > 0), r2 = (h < HH - 1);
    bool rowok[3] = { r0, true, r2 };
    #pragma unroll
    for (int kh = 0; kh < 3; ++kh) {
        if (rowok[kh]) {
            if (t < 2 * NWORD) {
                int c = (t < NWORD) ? 0 : (WPAD - 1);
                xs[kh][c * NWORD + (t & (NWORD - 1))] = 0u;
            }
            const uint32_t* src = &g_xp[((size_t)(n * HH + (h + kh - 1)) * WW) * NWORD];
            for (int i = t; i < WW * NWORD; i += 256)
                xs[kh][NWORD + i] = src[i];
        } else {
            for (int i = t; i < WPAD * NWORD; i += 256)
                xs[kh][i] = 0u;
        }
    }
    __syncthreads();

    // Folded epilogue: out = accx*(-2*iv) + c, accx = total popc(x^w), 72 words
    float iv = gamma[t] * rsqrtf(rvar[t] + BN_EPS);
    float bs = fmaf(-rmean[t], iv, beta[t]);
    int rowcnt    = (int)r0 + 1 + (int)r2;
    int Minv_base = (r0 ? 0 : (m[0] + m[1] + m[2])) + (r2 ? 0 : (m[6] + m[7] + m[8]));
    int Mleft     = (r0 ? m[0] : 0) + m[3] + (r2 ? m[6] : 0);
    int Mright    = (r0 ? m[2] : 0) + m[5] + (r2 ? m[8] : 0);
    int nv_base   = 3 * rowcnt;
    float niv2    = -2.0f * iv;
    float c_mid   = fmaf((float)(4608 - 2 * Minv_base - 256 * nv_base), iv, bs);
    float c_left  = fmaf((float)(4608 - 2 * (Minv_base + Mleft)  - 256 * (nv_base - rowcnt)), iv, bs);
    float c_right = fmaf((float)(4608 - 2 * (Minv_base + Mright) - 256 * (nv_base - rowcnt)), iv, bs);

    float* orow = os + t * OSROW;

    #pragma unroll 2
    for (int w = 0; w < WW; ++w) {
        int accx = 0;
        #pragma unroll
        for (int kh = 0; kh < 3; ++kh) {
            #pragma unroll
            for (int kw = 0; kw < 3; ++kw) {
                const uint4* p = (const uint4*)&xs[kh][(w + kw) * NWORD];
                uint4 a = p[0];
                uint4 c = p[1];
                const uint32_t* wr = wreg[kh * 3 + kw];
                accx += __popc(a.x ^ wr[0]) + __popc(a.y ^ wr[1])
                      + __popc(a.z ^ wr[2]) + __popc(a.w ^ wr[3])
                      + __popc(c.x ^ wr[4]) + __popc(c.y ^ wr[5])
                      + __popc(c.z ^ wr[6]) + __popc(c.w ^ wr[7]);
            }
        }
        float cb = c_mid;
        if (w == 0)      cb = c_left;
        if (w == WW - 1) cb = c_right;
        orow[w] = fmaf((float)accx, niv2, cb);      // STS, conflict-free (stride 57)
    }
    __syncthreads();

    // Coalesced writeback: consecutive threads -> consecutive w within a co row
    float* obase = out + ((size_t)n * COUT) * (HH * WW) + (size_t)h * WW;
    for (int i = t; i < COUT * WW; i += 256) {
        int co = i / WW, w = i - co * WW;
        obase[(size_t)co * (HH * WW) + w] = os[co * OSROW + w];
    }
}

// ---------------------------------------------------------------------------
extern "C" void kernel_launch(void* const* d_in, const int* in_sizes, int n_in,
                              void* d_out, int out_size) {
    const float* x     = (const float*)d_in[0];
    const float* wt    = (const float*)d_in[1];
    const float* gamma = (const float*)d_in[2];
    const float* beta  = (const float*)d_in[3];
    const float* rmean = (const float*)d_in[4];
    const float* rvar  = (const float*)d_in[5];
    float* out = (float*)d_out;

    cudaFuncSetAttribute(conv_kernel,
                         cudaFuncAttributeMaxDynamicSharedMemorySize, SMEM_DYN);

    pack_x_kernel<<<NB * HH, 512>>>(x);
    pack_w_kernel<<<(9 * NWORD * COUT + 255) / 256, 256>>>(wt);
    conv_kernel<<<NB * HH, 256, SMEM_DYN>>>(gamma, beta, rmean, rvar, out);
}

// round 12
// speedup vs baseline: 1.2971x; 1.2072x over previous
#include <cuda_runtime.h>
#include <stdint.h>

// Problem constants
#define NB    32
#define CIN   256
#define HH    56
#define WW    56
#define COUT  256
#define HW    3136
#define MTOT  100352              // 32*3136 = 784*128
#define KSTEPS 72                 // 9 taps * 8 ci-chunks of 32
#define BN_EPS 1e-5f

// smem: A bufs 2x(128x48B), B bufs 2x(128x48B), epi 128x129 floats
#define SM_B0   12288
#define SM_EPI  24576
#define EPI_STRIDE 129
#define SMEM_DYN (24576 + 128 * EPI_STRIDE * 4)   // 90624

// Scratch (no allocations): int8 signs
__device__ __align__(16) int8_t g_xs[(size_t)MTOT * CIN];        // NHWC [pix][ci]
__device__ __align__(16) int8_t g_ws[(size_t)COUT * 9 * CIN];    // [co][tap][ci]

// ---------------------------------------------------------------------------
// Pack x -> int8 signs, NHWC. Block per (n,h); thread t -> (wd=t/56, w=t%56).
// ---------------------------------------------------------------------------
__global__ void pack_xs_kernel(const float* __restrict__ x) {
    int b = blockIdx.x;            // n*56 + h
    int n = b / HH, h = b % HH;
    int t = threadIdx.x;
    if (t >= WW * 8) return;
    int wd = t / WW;               // ci block of 32
    int w  = t % WW;
    const float* xb = x + ((size_t)n * CIN + (size_t)wd * 32) * HW + (size_t)h * WW + w;
    uint32_t wv[8];
    #pragma unroll
    for (int j = 0; j < 8; ++j) {
        uint32_t acc = 0;
        #pragma unroll
        for (int c = 0; c < 4; ++c) {
            float v = __ldg(xb + (size_t)(j * 4 + c) * HW);
            uint32_t byte = (v > 0.0f) ? 0x01u : 0xFFu;
            acc |= byte << (8 * c);
        }
        wv[j] = acc;
    }
    size_t pix = (size_t)b * WW + w;
    uint4* dst = (uint4*)(g_xs + pix * CIN + wd * 32);
    dst[0] = make_uint4(wv[0], wv[1], wv[2], wv[3]);
    dst[1] = make_uint4(wv[4], wv[5], wv[6], wv[7]);
}

// ---------------------------------------------------------------------------
// Pack w -> int8 signs [co][tap][ci]. idx = co*2304 + tap*256 + ci.
// ---------------------------------------------------------------------------
__global__ void pack_ws_kernel(const float* __restrict__ wt) {
    int idx = blockIdx.x * 256 + threadIdx.x;    // < 256*2304
    int co = idx / (9 * CIN);
    int r  = idx - co * (9 * CIN);
    int tap = r >> 8, ci = r & 255;
    float v = __ldg(wt + ((size_t)co * CIN + ci) * 9 + tap);
    g_ws[idx] = (v > 0.0f) ? (int8_t)1 : (int8_t)-1;
}

// ---------------------------------------------------------------------------
// Implicit-GEMM binary conv via warp-level mma.sync m16n8k32 s8.
// CTA: 128 pixels x 128 cout; 8 warps of 32x64; 72 K-steps.
// Staging: plain LDG->reg prefetch -> STS double buffer (no cp.async).
// Only inline asm: the mma.sync itself.
// ---------------------------------------------------------------------------
__global__ void __launch_bounds__(256, 2)
conv_imma_kernel(const float* __restrict__ gamma, const float* __restrict__ beta,
                 const float* __restrict__ rmean, const float* __restrict__ rvar,
                 float* __restrict__ out) {
    extern __shared__ char sm[];
    __shared__ float ivs[128], bss[128];

    int tid = threadIdx.x, lane = tid & 31, wid = tid >> 5;
    int bid = blockIdx.x;
    int mb  = (bid >> 1) * 128;                 // pixel base
    int cob = (bid & 1) * 128;                  // cout base

    if (tid < 128) {
        int co = cob + tid;
        float iv = gamma[co] * rsqrtf(rvar[co] + BN_EPS);
        ivs[tid] = iv;
        bss[tid] = fmaf(-rmean[co], iv, beta[co]);
    }

    // staging role: row = tid/2 (0..127), 16B half = tid&1
    int srow = tid >> 1, shalf = tid & 1;
    int am = mb + srow;
    int an = am / HW; int ahw = am - an * HW;
    int ah = ahw / WW, aw = ahw - ah * WW;
    const int8_t* bwrow = g_ws + (size_t)(cob + srow) * 9 * CIN + shalf * 16;
    const int8_t* axbase = g_xs + (size_t)an * HW * CIN + shalf * 16;

    // prefetch regs for step s
    uint4 ra, rb;
#define LOADSTEP(s) do {                                                      \
    int tap = (s) >> 3, ci0 = ((s) & 7) * 32;                                 \
    int dh = tap / 3 - 1, dw = tap - (tap / 3) * 3 - 1;                       \
    int hp = ah + dh, wp = aw + dw;                                           \
    if ((unsigned)hp < (unsigned)HH && (unsigned)wp < (unsigned)WW)           \
        ra = *(const uint4*)(axbase + (size_t)(hp * WW + wp) * CIN + ci0);    \
    else                                                                      \
        ra = make_uint4(0u, 0u, 0u, 0u);                                      \
    rb = *(const uint4*)(bwrow + (size_t)tap * CIN + ci0);                    \
} while (0)

    // fragment geometry (48B row stride -> conflict-free)
    int g = lane >> 2, q = lane & 3;
    int warp_m = (wid & 3) * 32, warp_n = (wid >> 2) * 64;

    int acc[2][8][4];
    #pragma unroll
    for (int i = 0; i < 2; ++i)
        #pragma unroll
        for (int j = 0; j < 8; ++j)
            #pragma unroll
            for (int k = 0; k < 4; ++k) acc[i][j][k] = 0;

    LOADSTEP(0);

    for (int s = 0; s < KSTEPS; ++s) {
        char* abuf = sm + (s & 1) * 6144;
        char* bbuf = sm + SM_B0 + (s & 1) * 6144;

        // store staged regs for step s
        *(uint4*)(abuf + srow * 48 + shalf * 16) = ra;
        *(uint4*)(bbuf + srow * 48 + shalf * 16) = rb;
        __syncthreads();

        // prefetch step s+1 (latency hidden under LDS+MMA below)
        if (s + 1 < KSTEPS) LOADSTEP(s + 1);

        // fragment loads (plain C++ shared loads)
        uint32_t A[2][4], B[8][2];
        #pragma unroll
        for (int ma = 0; ma < 2; ++ma) {
            const char* base = abuf + (warp_m + ma * 16 + g) * 48 + 4 * q;
            A[ma][0] = *(const uint32_t*)(base);
            A[ma][1] = *(const uint32_t*)(base + 8 * 48);
            A[ma][2] = *(const uint32_t*)(base + 16);
            A[ma][3] = *(const uint32_t*)(base + 8 * 48 + 16);
        }
        #pragma unroll
        for (int na = 0; na < 8; ++na) {
            const char* base = bbuf + (warp_n + na * 8 + g) * 48 + 4 * q;
            B[na][0] = *(const uint32_t*)(base);
            B[na][1] = *(const uint32_t*)(base + 16);
        }

        #pragma unroll
        for (int ma = 0; ma < 2; ++ma)
            #pragma unroll
            for (int na = 0; na < 8; ++na)
                asm volatile(
                    "mma.sync.aligned.m16n8k32.row.col.s32.s8.s8.s32 "
                    "{%0,%1,%2,%3}, {%4,%5,%6,%7}, {%8,%9}, {%0,%1,%2,%3};"
                    : "+r"(acc[ma][na][0]), "+r"(acc[ma][na][1]),
                      "+r"(acc[ma][na][2]), "+r"(acc[ma][na][3])
                    : "r"(A[ma][0]), "r"(A[ma][1]), "r"(A[ma][2]), "r"(A[ma][3]),
                      "r"(B[na][0]), "r"(B[na][1]));
        __syncthreads();
    }

    // Epilogue: BN fold, stage [co][m] (stride 129 floats), coalesced writeback
    float* epi = (float*)(sm + SM_EPI);
    #pragma unroll
    for (int ma = 0; ma < 2; ++ma) {
        int m0 = warp_m + ma * 16 + g;
        #pragma unroll
        for (int na = 0; na < 8; ++na) {
            int c0 = warp_n + na * 8 + 2 * q;
            epi[(c0    ) * EPI_STRIDE + m0    ] = fmaf((float)acc[ma][na][0], ivs[c0],     bss[c0]);
            epi[(c0 + 1) * EPI_STRIDE + m0    ] = fmaf((float)acc[ma][na][1], ivs[c0 + 1], bss[c0 + 1]);
            epi[(c0    ) * EPI_STRIDE + m0 + 8] = fmaf((float)acc[ma][na][2], ivs[c0],     bss[c0]);
            epi[(c0 + 1) * EPI_STRIDE + m0 + 8] = fmaf((float)acc[ma][na][3], ivs[c0 + 1], bss[c0 + 1]);
        }
    }
    __syncthreads();

    // writeback: warp handles co = wid + 8*cc; lanes sweep m (coalesced STG)
    for (int cc = 0; cc < 16; ++cc) {
        int col = wid + cc * 8;
        size_t cog = cob + col;
        #pragma unroll
        for (int mmi = 0; mmi < 4; ++mmi) {
            int ml = mmi * 32 + lane;
            int m  = mb + ml;
            int n2 = m / HW; int hw = m - n2 * HW;
            out[(size_t)n2 * COUT * HW + cog * HW + hw] = epi[col * EPI_STRIDE + ml];
        }
    }
}

// ---------------------------------------------------------------------------
extern "C" void kernel_launch(void* const* d_in, const int* in_sizes, int n_in,
                              void* d_out, int out_size) {
    const float* x     = (const float*)d_in[0];
    const float* wt    = (const float*)d_in[1];
    const float* gamma = (const float*)d_in[2];
    const float* beta  = (const float*)d_in[3];
    const float* rmean = (const float*)d_in[4];
    const float* rvar  = (const float*)d_in[5];
    float* out = (float*)d_out;

    cudaFuncSetAttribute(conv_imma_kernel,
                         cudaFuncAttributeMaxDynamicSharedMemorySize, SMEM_DYN);

    pack_xs_kernel<<<NB * HH, 512>>>(x);
    pack_ws_kernel<<<9 * COUT, 256>>>(wt);
    conv_imma_kernel<<<784 * 2, 256, SMEM_DYN>>>(gamma, beta, rmean, rvar, out);
}

// round 13
// speedup vs baseline: 1.8173x; 1.4011x over previous
#include <cuda_runtime.h>
#include <cuda_pipeline.h>
#include <stdint.h>

// Problem constants
#define NB    32
#define CIN   256
#define HH    56
#define WW    56
#define COUT  256
#define HW    3136
#define MTOT  100352              // 32*3136 = 784*128
#define NSTEP 36                  // 9 taps * 4 ci-chunks of 64
#define BN_EPS 1e-5f

// smem: 4-stage ring, each stage 128 rows x 80B for A and B
#define STG_SZ   10240            // 128*80
#define SM_B0    40960            // 4*STG_SZ
#define EPI_STRIDE 129
#define SMEM_DYN 81920            // ring (81920) >= epi (66048), shared region

// Scratch (no allocations): int8 signs
__device__ __align__(16) int8_t g_xs[(size_t)MTOT * CIN];        // NHWC [pix][ci]
__device__ __align__(16) int8_t g_ws[(size_t)COUT * 9 * CIN];    // [co][tap][ci]

// ---------------------------------------------------------------------------
__global__ void pack_xs_kernel(const float* __restrict__ x) {
    int b = blockIdx.x;            // n*56 + h
    int n = b / HH, h = b % HH;
    int t = threadIdx.x;
    if (t >= WW * 8) return;
    int wd = t / WW;               // ci block of 32
    int w  = t % WW;
    const float* xb = x + ((size_t)n * CIN + (size_t)wd * 32) * HW + (size_t)h * WW + w;
    uint32_t wv[8];
    #pragma unroll
    for (int j = 0; j < 8; ++j) {
        uint32_t acc = 0;
        #pragma unroll
        for (int c = 0; c < 4; ++c) {
            float v = __ldg(xb + (size_t)(j * 4 + c) * HW);
            uint32_t byte = (v > 0.0f) ? 0x01u : 0xFFu;
            acc |= byte << (8 * c);
        }
        wv[j] = acc;
    }
    size_t pix = (size_t)b * WW + w;
    uint4* dst = (uint4*)(g_xs + pix * CIN + wd * 32);
    dst[0] = make_uint4(wv[0], wv[1], wv[2], wv[3]);
    dst[1] = make_uint4(wv[4], wv[5], wv[6], wv[7]);
}

// ---------------------------------------------------------------------------
__global__ void pack_ws_kernel(const float* __restrict__ wt) {
    int idx = blockIdx.x * 256 + threadIdx.x;    // < 256*2304
    int co = idx / (9 * CIN);
    int r  = idx - co * (9 * CIN);
    int tap = r >> 8, ci = r & 255;
    float v = __ldg(wt + ((size_t)co * CIN + ci) * 9 + tap);
    g_ws[idx] = (v > 0.0f) ? (int8_t)1 : (int8_t)-1;
}

// ---------------------------------------------------------------------------
// Implicit-GEMM binary conv via mma.sync m16n8k32 s8.
// CTA 128x128; 8 warps (32x64 each); 36 K-iters of 64 ci; 4-stage
// cp.async ring (__pipeline intrinsics), ONE __syncthreads per iter.
// ---------------------------------------------------------------------------
__global__ void __launch_bounds__(256, 2)
conv_imma_kernel(const float* __restrict__ gamma, const float* __restrict__ beta,
                 const float* __restrict__ rmean, const float* __restrict__ rvar,
                 float* __restrict__ out) {
    extern __shared__ char sm[];
    __shared__ float ivs[128], bss[128];

    int tid = threadIdx.x, lane = tid & 31, wid = tid >> 5;
    int bid = blockIdx.x;
    int mb  = (bid >> 1) * 128;                 // pixel base
    int cob = (bid & 1) * 128;                  // cout base

    if (tid < 128) {
        int co = cob + tid;
        float iv = gamma[co] * rsqrtf(rvar[co] + BN_EPS);
        ivs[tid] = iv;
        bss[tid] = fmaf(-rmean[co], iv, beta[co]);
    }

    // staging role: row = tid/2 (0..127), 32B half = tid&1
    int srow = tid >> 1, shalf = tid & 1;
    int am = mb + srow;
    int an = am / HW; int ahw = am - an * HW;
    int ah = ahw / WW, aw = ahw - ah * WW;
    const int8_t* axbase = g_xs + (size_t)an * HW * CIN;
    const int8_t* bwrow  = g_ws + (size_t)(cob + srow) * 9 * CIN;

#define STAGEOP(s) do {                                                       \
    int tap = (s) >> 2, cq = (s) & 3;                                         \
    int ci0 = cq * 64 + shalf * 32;                                           \
    int dh = tap / 3 - 1, dw = tap - (tap / 3) * 3 - 1;                       \
    int hp = ah + dh, wp = aw + dw;                                           \
    bool okp = ((unsigned)hp < (unsigned)HH && (unsigned)wp < (unsigned)WW);  \
    int hc = hp < 0 ? 0 : (hp > 55 ? 55 : hp);                                \
    int wc = wp < 0 ? 0 : (wp > 55 ? 55 : wp);                                \
    const int8_t* ga = axbase + (size_t)(hc * WW + wc) * CIN + ci0;           \
    char* ad = sm + ((s) & 3) * STG_SZ + srow * 80 + shalf * 32;              \
    size_t zf = okp ? 0 : 16;                                                 \
    __pipeline_memcpy_async(ad,      ga,      16, zf);                        \
    __pipeline_memcpy_async(ad + 16, ga + 16, 16, zf);                        \
    const int8_t* gb = bwrow + (size_t)tap * CIN + ci0;                       \
    char* bd = sm + SM_B0 + ((s) & 3) * STG_SZ + srow * 80 + shalf * 32;      \
    __pipeline_memcpy_async(bd,      gb,      16, 0);                         \
    __pipeline_memcpy_async(bd + 16, gb + 16, 16, 0);                         \
} while (0)

    // fragment geometry (80B row stride -> conflict-free)
    int g = lane >> 2, q = lane & 3;
    int warp_m = (wid & 3) * 32, warp_n = (wid >> 2) * 64;

    int acc[2][8][4];
    #pragma unroll
    for (int i = 0; i < 2; ++i)
        #pragma unroll
        for (int j = 0; j < 8; ++j)
            #pragma unroll
            for (int k = 0; k < 4; ++k) acc[i][j][k] = 0;

    STAGEOP(0); __pipeline_commit();
    STAGEOP(1); __pipeline_commit();
    STAGEOP(2); __pipeline_commit();

    for (int s = 0; s < NSTEP; ++s) {
        __pipeline_wait_prior(2);               // stage s landed (this thread)
        __syncthreads();                        // ... and all threads'

        const char* abuf = sm + (s & 3) * STG_SZ;
        const char* bbuf = sm + SM_B0 + (s & 3) * STG_SZ;

        #pragma unroll
        for (int kc = 0; kc < 2; ++kc) {
            uint32_t A[2][4], B[8][2];
            #pragma unroll
            for (int ma = 0; ma < 2; ++ma) {
                const char* base = abuf + (warp_m + ma * 16 + g) * 80 + kc * 32 + 4 * q;
                A[ma][0] = *(const uint32_t*)(base);
                A[ma][1] = *(const uint32_t*)(base + 8 * 80);
                A[ma][2] = *(const uint32_t*)(base + 16);
                A[ma][3] = *(const uint32_t*)(base + 8 * 80 + 16);
            }
            #pragma unroll
            for (int na = 0; na < 8; ++na) {
                const char* base = bbuf + (warp_n + na * 8 + g) * 80 + kc * 32 + 4 * q;
                B[na][0] = *(const uint32_t*)(base);
                B[na][1] = *(const uint32_t*)(base + 16);
            }
            #pragma unroll
            for (int ma = 0; ma < 2; ++ma)
                #pragma unroll
                for (int na = 0; na < 8; ++na)
                    asm volatile(
                        "mma.sync.aligned.m16n8k32.row.col.s32.s8.s8.s32 "
                        "{%0,%1,%2,%3}, {%4,%5,%6,%7}, {%8,%9}, {%0,%1,%2,%3};"
                        : "+r"(acc[ma][na][0]), "+r"(acc[ma][na][1]),
                          "+r"(acc[ma][na][2]), "+r"(acc[ma][na][3])
                        : "r"(A[ma][0]), "r"(A[ma][1]), "r"(A[ma][2]), "r"(A[ma][3]),
                          "r"(B[na][0]), "r"(B[na][1]));
        }

        // stage s+3 into buf[(s-1)&3]; the sync above ordered it vs iter s-1 reads
        if (s + 3 < NSTEP) STAGEOP(s + 3);
        __pipeline_commit();                    // always commit (keeps wait_prior sound)
    }

    __pipeline_wait_prior(0);
    __syncthreads();                            // accs in regs; ring now reusable

    // Epilogue: BN fold, stage [co][m] (stride 129 floats), coalesced writeback
    float* epi = (float*)sm;
    #pragma unroll
    for (int ma = 0; ma < 2; ++ma) {
        int m0 = warp_m + ma * 16 + g;
        #pragma unroll
        for (int na = 0; na < 8; ++na) {
            int c0 = warp_n + na * 8 + 2 * q;
            epi[(c0    ) * EPI_STRIDE + m0    ] = fmaf((float)acc[ma][na][0], ivs[c0],     bss[c0]);
            epi[(c0 + 1) * EPI_STRIDE + m0    ] = fmaf((float)acc[ma][na][1], ivs[c0 + 1], bss[c0 + 1]);
            epi[(c0    ) * EPI_STRIDE + m0 + 8] = fmaf((float)acc[ma][na][2], ivs[c0],     bss[c0]);
            epi[(c0 + 1) * EPI_STRIDE + m0 + 8] = fmaf((float)acc[ma][na][3], ivs[c0 + 1], bss[c0 + 1]);
        }
    }
    __syncthreads();

    // writeback: warp handles co = wid + 8*cc; lanes sweep m (coalesced STG)
    for (int cc = 0; cc < 16; ++cc) {
        int col = wid + cc * 8;
        size_t cog = cob + col;
        #pragma unroll
        for (int mmi = 0; mmi < 4; ++mmi) {
            int ml = mmi * 32 + lane;
            int m  = mb + ml;
            int n2 = m / HW; int hw = m - n2 * HW;
            out[(size_t)n2 * COUT * HW + cog * HW + hw] = epi[col * EPI_STRIDE + ml];
        }
    }
}

// ---------------------------------------------------------------------------
extern "C" void kernel_launch(void* const* d_in, const int* in_sizes, int n_in,
                              void* d_out, int out_size) {
    const float* x     = (const float*)d_in[0];
    const float* wt    = (const float*)d_in[1];
    const float* gamma = (const float*)d_in[2];
    const float* beta  = (const float*)d_in[3];
    const float* rmean = (const float*)d_in[4];
    const float* rvar  = (const float*)d_in[5];
    float* out = (float*)d_out;

    cudaFuncSetAttribute(conv_imma_kernel,
                         cudaFuncAttributeMaxDynamicSharedMemorySize, SMEM_DYN);

    pack_xs_kernel<<<NB * HH, 512>>>(x);
    pack_ws_kernel<<<9 * COUT, 256>>>(wt);
    conv_imma_kernel<<<784 * 2, 256, SMEM_DYN>>>(gamma, beta, rmean, rvar, out);
}

// round 14
// speedup vs baseline: 1.8742x; 1.0313x over previous
#include <cuda_runtime.h>
#include <cuda_pipeline.h>
#include <stdint.h>

// Problem constants
#define NB    32
#define CIN   256
#define HH    56
#define WW    56
#define COUT  256
#define HW    3136
#define MTOT  100352              // 32*3136 = 784*128
#define NSTEP 18                  // 9 taps * 2 ci-chunks of 128
#define BN_EPS 1e-5f

// smem: 3-stage ring; stage = A(128x144B) + B(128x144B)
#define ROWB    144
#define STG_A   18432             // 128*144
#define STG_SZ  36864             // A+B per stage
#define EPI_STRIDE 129
#define SMEM_DYN (3 * STG_SZ)     // 110592; epi (66048) reuses this region

// Scratch (no allocations): int8 signs
__device__ __align__(16) int8_t g_xs[(size_t)MTOT * CIN];        // NHWC [pix][ci]
__device__ __align__(16) int8_t g_ws[(size_t)COUT * 9 * CIN];    // [co][tap][ci]

__device__ __forceinline__ uint32_t smem_u32(const void* p) {
    uint32_t a;
    asm("{ .reg .u64 t; cvta.to.shared.u64 t, %1; cvt.u32.u64 %0, t; }"
        : "=r"(a) : "l"(p));
    return a;
}

// ---------------------------------------------------------------------------
__global__ void pack_xs_kernel(const float* __restrict__ x) {
    int b = blockIdx.x;            // n*56 + h
    int n = b / HH, h = b % HH;
    int t = threadIdx.x;
    if (t >= WW * 8) return;
    int wd = t / WW;               // ci block of 32
    int w  = t % WW;
    const float* xb = x + ((size_t)n * CIN + (size_t)wd * 32) * HW + (size_t)h * WW + w;
    uint32_t wv[8];
    #pragma unroll
    for (int j = 0; j < 8; ++j) {
        uint32_t acc = 0;
        #pragma unroll
        for (int c = 0; c < 4; ++c) {
            float v = __ldg(xb + (size_t)(j * 4 + c) * HW);
            uint32_t byte = (v > 0.0f) ? 0x01u : 0xFFu;
            acc |= byte << (8 * c);
        }
        wv[j] = acc;
    }
    size_t pix = (size_t)b * WW + w;
    uint4* dst = (uint4*)(g_xs + pix * CIN + wd * 32);
    dst[0] = make_uint4(wv[0], wv[1], wv[2], wv[3]);
    dst[1] = make_uint4(wv[4], wv[5], wv[6], wv[7]);
}

// ---------------------------------------------------------------------------
__global__ void pack_ws_kernel(const float* __restrict__ wt) {
    int idx = blockIdx.x * 256 + threadIdx.x;    // < 256*2304
    int co = idx / (9 * CIN);
    int r  = idx - co * (9 * CIN);
    int tap = r >> 8, ci = r & 255;
    float v = __ldg(wt + ((size_t)co * CIN + ci) * 9 + tap);
    g_ws[idx] = (v > 0.0f) ? (int8_t)1 : (int8_t)-1;
}

// ---------------------------------------------------------------------------
// Implicit-GEMM binary conv via mma.sync m16n8k32 s8 + ldmatrix frag loads.
// CTA 128x128; 8 warps (32x64); 18 K-iters of 128 ci; 3-stage cp.async ring.
// ---------------------------------------------------------------------------
__global__ void __launch_bounds__(256, 2)
conv_imma_kernel(const float* __restrict__ gamma, const float* __restrict__ beta,
                 const float* __restrict__ rmean, const float* __restrict__ rvar,
                 float* __restrict__ out) {
    extern __shared__ char sm[];
    __shared__ float ivs[128], bss[128];

    int tid = threadIdx.x, lane = tid & 31, wid = tid >> 5;
    int bid = blockIdx.x;
    int mb  = (bid >> 1) * 128;                 // pixel base
    int cob = (bid & 1) * 128;                  // cout base
    uint32_t smb = smem_u32(sm);

    if (tid < 128) {
        int co = cob + tid;
        float iv = gamma[co] * rsqrtf(rvar[co] + BN_EPS);
        ivs[tid] = iv;
        bss[tid] = fmaf(-rmean[co], iv, beta[co]);
    }

    // staging role: row = tid/2 (0..127), 64B seg = tid&1
    int srow = tid >> 1, shalf = tid & 1;
    int am = mb + srow;
    int an = am / HW; int ahw = am - an * HW;
    int ah = ahw / WW, aw = ahw - ah * WW;
    const int8_t* axbase = g_xs + (size_t)an * HW * CIN;
    const int8_t* bwrow  = g_ws + (size_t)(cob + srow) * 9 * CIN;

#define STAGEOP(s) do {                                                       \
    int tap = (s) >> 1;                                                       \
    int ci0 = ((s) & 1) * 128 + shalf * 64;                                   \
    int dh = tap / 3 - 1, dw = tap - (tap / 3) * 3 - 1;                       \
    int hp = ah + dh, wp = aw + dw;                                           \
    bool okp = ((unsigned)hp < (unsigned)HH && (unsigned)wp < (unsigned)WW);  \
    int hc = hp < 0 ? 0 : (hp > 55 ? 55 : hp);                                \
    int wc = wp < 0 ? 0 : (wp > 55 ? 55 : wp);                                \
    const int8_t* ga = axbase + (size_t)(hc * WW + wc) * CIN + ci0;           \
    char* ad = sm + ((s) % 3) * STG_SZ + srow * ROWB + shalf * 64;            \
    size_t zf = okp ? 0 : 16;                                                 \
    __pipeline_memcpy_async(ad,      ga,      16, zf);                        \
    __pipeline_memcpy_async(ad + 16, ga + 16, 16, zf);                        \
    __pipeline_memcpy_async(ad + 32, ga + 32, 16, zf);                        \
    __pipeline_memcpy_async(ad + 48, ga + 48, 16, zf);                        \
    const int8_t* gb = bwrow + (size_t)tap * CIN + ci0;                       \
    char* bd = sm + ((s) % 3) * STG_SZ + STG_A + srow * ROWB + shalf * 64;    \
    __pipeline_memcpy_async(bd,      gb,      16, 0);                         \
    __pipeline_memcpy_async(bd + 16, gb + 16, 16, 0);                         \
    __pipeline_memcpy_async(bd + 32, gb + 32, 16, 0);                         \
    __pipeline_memcpy_async(bd + 48, gb + 48, 16, 0);                         \
} while (0)

    // fragment geometry
    int g = lane >> 2, q = lane & 3;
    int warp_m = (wid & 3) * 32, warp_n = (wid >> 2) * 64;

    // per-lane ldmatrix row offsets (relative to stage base, before kc*32)
    // A: tiles {rows 0-7, 8-15} x {bytes 0-15, 16-31}
    uint32_t aoff = (uint32_t)((warp_m + (lane & 15)) * ROWB + (lane >> 4) * 16);
    // B: tiles {rows R..R+7 b0-15, R..R+7 b16-31, R+8.. b0-15, R+8.. b16-31}
    uint32_t boff = (uint32_t)((warp_n + (lane & 7) + ((lane >> 4) << 3)) * ROWB
                               + ((lane >> 3) & 1) * 16);

    int acc[2][8][4];
    #pragma unroll
    for (int i = 0; i < 2; ++i)
        #pragma unroll
        for (int j = 0; j < 8; ++j)
            #pragma unroll
            for (int k = 0; k < 4; ++k) acc[i][j][k] = 0;

    STAGEOP(0); __pipeline_commit();
    STAGEOP(1); __pipeline_commit();

    for (int s = 0; s < NSTEP; ++s) {
        __pipeline_wait_prior(1);               // stage s landed (this thread)
        __syncthreads();                        // ... and all threads'

        uint32_t abase = smb + (s % 3) * STG_SZ;
        uint32_t bbase = abase + STG_A;

        #pragma unroll
        for (int kc = 0; kc < 4; ++kc) {
            uint32_t A[2][4], B[8][2];
            #pragma unroll
            for (int ma = 0; ma < 2; ++ma) {
                uint32_t addr = abase + aoff + ma * 16 * ROWB + kc * 32;
                asm volatile(
                    "ldmatrix.sync.aligned.m8n8.x4.shared.b16 {%0,%1,%2,%3}, [%4];"
                    : "=r"(A[ma][0]), "=r"(A[ma][1]), "=r"(A[ma][2]), "=r"(A[ma][3])
                    : "r"(addr));
            }
            #pragma unroll
            for (int nb = 0; nb < 4; ++nb) {
                uint32_t addr = bbase + boff + nb * 16 * ROWB + kc * 32;
                asm volatile(
                    "ldmatrix.sync.aligned.m8n8.x4.shared.b16 {%0,%1,%2,%3}, [%4];"
                    : "=r"(B[2 * nb][0]), "=r"(B[2 * nb][1]),
                      "=r"(B[2 * nb + 1][0]), "=r"(B[2 * nb + 1][1])
                    : "r"(addr));
            }
            #pragma unroll
            for (int ma = 0; ma < 2; ++ma)
                #pragma unroll
                for (int na = 0; na < 8; ++na)
                    asm volatile(
                        "mma.sync.aligned.m16n8k32.row.col.s32.s8.s8.s32 "
                        "{%0,%1,%2,%3}, {%4,%5,%6,%7}, {%8,%9}, {%0,%1,%2,%3};"
                        : "+r"(acc[ma][na][0]), "+r"(acc[ma][na][1]),
                          "+r"(acc[ma][na][2]), "+r"(acc[ma][na][3])
                        : "r"(A[ma][0]), "r"(A[ma][1]), "r"(A[ma][2]), "r"(A[ma][3]),
                          "r"(B[na][0]), "r"(B[na][1]));
        }

        // stage s+2 into buf[(s+2)%3]=buf[(s-1)%3]; sync above ordered it
        if (s + 2 < NSTEP) STAGEOP(s + 2);
        __pipeline_commit();                    // always commit (wait accounting)
    }

    __pipeline_wait_prior(0);
    __syncthreads();                            // accs in regs; ring reusable

    // Epilogue: BN fold, stage [co][m] (stride 129 floats), coalesced writeback
    float* epi = (float*)sm;
    #pragma unroll
    for (int ma = 0; ma < 2; ++ma) {
        int m0 = warp_m + ma * 16 + g;
        #pragma unroll
        for (int na = 0; na < 8; ++na) {
            int c0 = warp_n + na * 8 + 2 * q;
            epi[(c0    ) * EPI_STRIDE + m0    ] = fmaf((float)acc[ma][na][0], ivs[c0],     bss[c0]);
            epi[(c0 + 1) * EPI_STRIDE + m0    ] = fmaf((float)acc[ma][na][1], ivs[c0 + 1], bss[c0 + 1]);
            epi[(c0    ) * EPI_STRIDE + m0 + 8] = fmaf((float)acc[ma][na][2], ivs[c0],     bss[c0]);
            epi[(c0 + 1) * EPI_STRIDE + m0 + 8] = fmaf((float)acc[ma][na][3], ivs[c0 + 1], bss[c0 + 1]);
        }
    }
    __syncthreads();

    // writeback: warp handles co = wid + 8*cc; lanes sweep m (coalesced STG)
    for (int cc = 0; cc < 16; ++cc) {
        int col = wid + cc * 8;
        size_t cog = cob + col;
        #pragma unroll
        for (int mmi = 0; mmi < 4; ++mmi) {
            int ml = mmi * 32 + lane;
            int m  = mb + ml;
            int n2 = m / HW; int hw = m - n2 * HW;
            out[(size_t)n2 * COUT * HW + cog * HW + hw] = epi[col * EPI_STRIDE + ml];
        }
    }
}

// ---------------------------------------------------------------------------
extern "C" void kernel_launch(void* const* d_in, const int* in_sizes, int n_in,
                              void* d_out, int out_size) {
    const float* x     = (const float*)d_in[0];
    const float* wt    = (const float*)d_in[1];
    const float* gamma = (const float*)d_in[2];
    const float* beta  = (const float*)d_in[3];
    const float* rmean = (const float*)d_in[4];
    const float* rvar  = (const float*)d_in[5];
    float* out = (float*)d_out;

    cudaFuncSetAttribute(conv_imma_kernel,
                         cudaFuncAttributeMaxDynamicSharedMemorySize, SMEM_DYN);

    pack_xs_kernel<<<NB * HH, 512>>>(x);
    pack_ws_kernel<<<9 * COUT, 256>>>(wt);
    conv_imma_kernel<<<784 * 2, 256, SMEM_DYN>>>(gamma, beta, rmean, rvar, out);
}